// round 2
// baseline (speedup 1.0000x reference)
#include <cuda_runtime.h>
#include <cuda_bf16.h>
#include <cstdint>

// ---------------------------------------------------------------------------
// Fused PatchTransformer:
//   blocks [0, NMED)        : persistent median producers -> g_p + flags
//   blocks [NMED, NMED+NAPP): elementwise consumers, region-major order
// ---------------------------------------------------------------------------

#define PATCH 300
#define CH 3
#define BF_TOTAL 224                    // 16*14
#define PLANE (PATCH * PATCH)           // 90000
#define CHW (CH * PLANE)                // 270000

#define TBX 32
#define TBY 8
#define TILE_W (TBX + 6)   // 38
#define TILE_H (TBY + 6)   // 14
#define TILE_PITCH 40

#define XT 10              // x tiles per channel (ceil(300/32))
#define YT 38              // y tiles per channel (ceil(300/8))
#define TILES_PER_C (XT * YT)           // 380
#define NTILES (TILES_PER_C * CH)       // 1140
#define NMED 296

#define REG_SZ 2048
#define REGIONS 132        // ceil(270000/2048)
#define NAPP (BF_TOTAL * REGIONS)       // 29568
#define NFLAGS (CH * YT)   // 114

__device__ float g_p[CHW];
__device__ int   g_flags[NFLAGS];

// compare-exchange: a <- min, b <- max
__device__ __forceinline__ void s2(float& a, float& b) {
    float t = fminf(a, b);
    b = fmaxf(a, b);
    a = t;
}

// Bring min of a[0..N-1] to a[0] and max to a[N-1]; multiset preserved.
template <int N>
__device__ __forceinline__ void mnmx(float* a) {
#pragma unroll
    for (int i = 0; i < N / 2; i++) s2(a[i], a[N - 1 - i]);
#pragma unroll
    for (int i = 1; i < (N + 1) / 2; i++) s2(a[0], a[i]);
#pragma unroll
    for (int i = N - 2; i >= N / 2; i--) s2(a[i], a[N - 1]);
}

__device__ __forceinline__ int reflect_idx(int t) {
    t = (t < 0) ? -t : t;
    t = (t >= PATCH) ? (2 * PATCH - 2 - t) : t;
    return t;
}

// Forgetful selection: exact median of the 7x7 window at (tx, ty) in tile.
__device__ __forceinline__ float median49(const float tile[TILE_H][TILE_PITCH],
                                          int tx, int ty) {
    float a[26];
#pragma unroll
    for (int k = 0; k < 26; k++)
        a[k] = tile[ty + k / 7][tx + k % 7];

#pragma unroll
    for (int st = 0; st < 11; st++) {
        mnmx<26>(a);
        const int k0 = 26 + 2 * st;
        const int k1 = 27 + 2 * st;
        a[0]  = tile[ty + k0 / 7][tx + k0 % 7];
        a[25] = tile[ty + k1 / 7][tx + k1 % 7];
    }
    mnmx<26>(a);
    a[0] = tile[ty + 48 / 7][tx + 48 % 7];

    // 25 values remain, target rank 12: symmetric shrink.
    mnmx<25>(a);
    mnmx<23>(a + 1);
    mnmx<21>(a + 2);
    mnmx<19>(a + 3);
    mnmx<17>(a + 4);
    mnmx<15>(a + 5);
    mnmx<13>(a + 6);
    mnmx<11>(a + 7);
    mnmx<9>(a + 8);
    mnmx<7>(a + 9);
    mnmx<5>(a + 10);
    s2(a[11], a[12]);
    s2(a[12], a[13]);
    s2(a[11], a[12]);
    return a[12];
}

__global__ __launch_bounds__(256)
void fused_kernel(const float* __restrict__ adv,
                  const float4* __restrict__ noise,
                  const float* __restrict__ contrast,
                  const float* __restrict__ brightness,
                  float4* __restrict__ out) {
    __shared__ float tile[TILE_H][TILE_PITCH];

    const int bid = blockIdx.x;
    const int tid = threadIdx.x;

    if (bid < NMED) {
        // ---------------- median producer: tiles bid, bid+NMED, ... ----------
        for (int t = bid; t < NTILES; t += NMED) {
            const int c   = t / TILES_PER_C;
            const int rem = t - c * TILES_PER_C;
            const int yt  = rem / XT;
            const int xt  = rem - yt * XT;
            const int x0 = xt * TBX;
            const int y0 = yt * TBY;
            const float* s = adv + c * PLANE;

#pragma unroll
            for (int i = tid; i < TILE_W * TILE_H; i += 256) {
                const int lx = i % TILE_W;
                const int ly = i / TILE_W;
                const int gx = reflect_idx(x0 - 3 + lx);
                const int gy = reflect_idx(y0 - 3 + ly);
                tile[ly][lx] = s[gy * PATCH + gx];
            }
            __syncthreads();

            const int tx = tid & 31;
            const int ty = tid >> 5;
            const int ox = x0 + tx;
            const int oy = y0 + ty;
            if (ox < PATCH && oy < PATCH) {
                g_p[c * PLANE + oy * PATCH + ox] = median49(tile, tx, ty);
            }
            __threadfence();
            __syncthreads();                 // all stores fenced, smem reads done
            if (tid == 0) atomicAdd(&g_flags[c * YT + yt], 1);
        }
    } else {
        // ---------------- consumer: one (region, slab) --------------------
        const int ab = bid - NMED;
        const int r  = ab / BF_TOTAL;        // region-major: early bids -> region 0
        const int sl = ab - r * BF_TOTAL;

        const int base = r * REG_SZ;
        const int last = min(base + REG_SZ, CHW) - 1;

        if (tid == 0) {
            const int cA = base / PLANE;
            const int cB = last / PLANE;
            for (int c = cA; c <= cB; c++) {
                const int lo = max(base, c * PLANE) - c * PLANE;
                const int hi = min(last, c * PLANE + PLANE - 1) - c * PLANE;
                const int y0t = (lo / PATCH) / TBY;
                const int y1t = (hi / PATCH) / TBY;
                for (int yt = y0t; yt <= y1t; yt++) {
                    while (((volatile int*)g_flags)[c * YT + yt] < XT) { }
                }
            }
            __threadfence();
        }
        __syncthreads();

        const float cc = __ldg(&contrast[sl]);
        const float bb = __ldg(&brightness[sl]);
        const int slab_base = sl * CHW;

#pragma unroll
        for (int h = 0; h < 2; h++) {
            const int off = base + h * 1024 + tid * 4;
            if (off < CHW) {
                const float4 p = *reinterpret_cast<const float4*>(&g_p[off]);
                const int fi = (slab_base + off) >> 2;   // float4 index
                const float4 n = noise[fi];
                float4 rr;
                rr.x = fmaf(n.x, 0.1f, fmaf(p.x, cc, bb));
                rr.y = fmaf(n.y, 0.1f, fmaf(p.y, cc, bb));
                rr.z = fmaf(n.z, 0.1f, fmaf(p.z, cc, bb));
                rr.w = fmaf(n.w, 0.1f, fmaf(p.w, cc, bb));
                rr.x = fminf(fmaxf(rr.x, 1e-6f), 0.99999f);
                rr.y = fminf(fmaxf(rr.y, 1e-6f), 0.99999f);
                rr.z = fminf(fmaxf(rr.z, 1e-6f), 0.99999f);
                rr.w = fminf(fmaxf(rr.w, 1e-6f), 0.99999f);
                out[fi] = rr;
            }
        }
    }
}

// ---------------------------------------------------------------------------
// Inputs (metadata order):
//   0: adv_patch  [3,300,300] f32
//   1: lab_batch  [16,14,5]   f32 (unused)
//   2: contrast   [16,14]     f32
//   3: brightness [16,14]     f32
//   4: noise      [16,14,3,300,300] f32
//   5: img_size   scalar (unused)
// Output: [16,14,3,300,300] f32
// ---------------------------------------------------------------------------
extern "C" void kernel_launch(void* const* d_in, const int* in_sizes, int n_in,
                              void* d_out, int out_size) {
    const float* adv_patch  = (const float*)d_in[0];
    const float* contrast   = (const float*)d_in[2];
    const float* brightness = (const float*)d_in[3];
    const float* noise      = (const float*)d_in[4];
    float* out = (float*)d_out;

    void* flags_ptr = nullptr;
    cudaGetSymbolAddress(&flags_ptr, g_flags);
    cudaMemsetAsync(flags_ptr, 0, NFLAGS * sizeof(int));

    const int grid = NMED + NAPP;
    fused_kernel<<<grid, 256>>>(adv_patch, (const float4*)noise,
                                contrast, brightness, (float4*)out);
}

// round 3
// speedup vs baseline: 1.4146x; 1.4146x over previous
#include <cuda_runtime.h>
#include <cuda_bf16.h>
#include <cstdint>

// ---------------------------------------------------------------------------
// PatchTransformer, two kernels:
//   K1: exact 7x7 median (reflect pad) via column-sort + row-sort + band select
//   K2: streaming elementwise affine + noise + clip (HBM-bound)
// ---------------------------------------------------------------------------

#define PATCH 300
#define CH 3
#define BF_TOTAL 224                    // 16*14
#define PLANE (PATCH * PATCH)           // 90000
#define CHW (CH * PLANE)                // 270000

__device__ float g_p[CHW];

// compare-exchange: a <- min, b <- max
__device__ __forceinline__ void s2(float& a, float& b) {
    float t = fminf(a, b);
    b = fmaxf(a, b);
    a = t;
}

// Bring min of a[0..N-1] to a[0] and max to a[N-1]; multiset preserved.
template <int N>
__device__ __forceinline__ void mnmx(float* a) {
#pragma unroll
    for (int i = 0; i < N / 2; i++) s2(a[i], a[N - 1 - i]);
#pragma unroll
    for (int i = 1; i < (N + 1) / 2; i++) s2(a[0], a[i]);
#pragma unroll
    for (int i = N - 2; i >= N / 2; i--) s2(a[i], a[N - 1]);
}

// Exact 7-sorter: Batcher odd-even mergesort on 8 with a[7] = +inf pruned.
// 16 compare-exchanges, provably correct by monotone pruning of Batcher-8.
__device__ __forceinline__ void sort7(float* a) {
    s2(a[0], a[1]); s2(a[2], a[3]); s2(a[4], a[5]);
    s2(a[0], a[2]); s2(a[1], a[3]); s2(a[4], a[6]);
    s2(a[1], a[2]); s2(a[5], a[6]);
    s2(a[0], a[4]); s2(a[1], a[5]); s2(a[2], a[6]);
    s2(a[2], a[4]); s2(a[3], a[5]);
    s2(a[1], a[2]); s2(a[3], a[4]); s2(a[5], a[6]);
}

__device__ __forceinline__ int reflect_idx(int t) {
    t = (t < 0) ? -t : t;
    t = (t >= PATCH) ? (2 * PATCH - 2 - t) : t;
    return t;
}

// Tile: 32x8 outputs per block, halo 3 -> load 38x14 raw.
#define TBX 32
#define TBY 8
#define TILE_W (TBX + 6)   // 38
#define TILE_H (TBY + 6)   // 14
#define TILE_PITCH 40
#define NCOLTASK (TBY * TILE_W)   // 304 column sorts per block

__global__ __launch_bounds__(TBX * TBY)
void median7_kernel(const float* __restrict__ src) {
    __shared__ float tile[TILE_H][TILE_PITCH];
    __shared__ float scol[NCOLTASK][7];   // sorted 7-column per (yw, col)

    const int c  = blockIdx.z;
    const int x0 = blockIdx.x * TBX;
    const int y0 = blockIdx.y * TBY;
    const float* s = src + c * PLANE;

    const int tx  = threadIdx.x;
    const int ty  = threadIdx.y;
    const int tid = ty * TBX + tx;

    // ---- load raw tile with reflect padding ----
#pragma unroll
    for (int i = tid; i < TILE_W * TILE_H; i += TBX * TBY) {
        const int lx = i % TILE_W;
        const int ly = i / TILE_W;
        const int gx = reflect_idx(x0 - 3 + lx);
        const int gy = reflect_idx(y0 - 3 + ly);
        tile[ly][lx] = s[gy * PATCH + gx];
    }
    __syncthreads();

    // ---- phase A: sort all column windows (shared across x-neighbors) ----
    for (int t = tid; t < NCOLTASK; t += TBX * TBY) {
        const int yw  = t / TILE_W;
        const int col = t - yw * TILE_W;
        float a[7];
#pragma unroll
        for (int r = 0; r < 7; r++) a[r] = tile[yw + r][col];
        sort7(a);
#pragma unroll
        for (int k = 0; k < 7; k++) scol[t][k] = a[k];
    }
    __syncthreads();

    const int ox = x0 + tx;
    const int oy = y0 + ty;
    if (ox >= PATCH || oy >= PATCH) return;

    // ---- phase B: per-pixel row sort + band selection ----
    // Doubly-sorted 7x7: median of 49 == median of the 29-candidate band:
    //   i=0: j4..6 | i=1: j3..6 | i=2: j2..6 | i=3: j1..5
    //   i=4: j0..4 | i=5: j0..3 | i=6: j0..2
    const int base = ty * TILE_W + tx;

    float S[16];
    float r[7];

    // helper macro: load row i across the 7 sorted columns, sort it
#define LOAD_SORT_ROW(I)                                        \
    do {                                                        \
        _Pragma("unroll")                                       \
        for (int dx = 0; dx < 7; dx++) r[dx] = scol[base + dx][I]; \
        sort7(r);                                               \
    } while (0)

    LOAD_SORT_ROW(2);
    S[0] = r[2]; S[1] = r[3]; S[2] = r[4]; S[3] = r[5]; S[4] = r[6];
    LOAD_SORT_ROW(3);
    S[5] = r[1]; S[6] = r[2]; S[7] = r[3]; S[8] = r[4]; S[9] = r[5];
    LOAD_SORT_ROW(4);
    S[10] = r[0]; S[11] = r[1]; S[12] = r[2]; S[13] = r[3]; S[14] = r[4];
    LOAD_SORT_ROW(1);
    S[15] = r[3];
    float f0 = r[4], f1 = r[5], f2 = r[6];

    // forgetful selection: 7 steps, each discards provable min & max
    mnmx<16>(S); S[0] = f0; S[15] = f1;
    LOAD_SORT_ROW(5);
    mnmx<16>(S); S[0] = f2;   S[15] = r[0];
    mnmx<16>(S); S[0] = r[1]; S[15] = r[2];
    float f3 = r[3];
    LOAD_SORT_ROW(0);
    mnmx<16>(S); S[0] = f3;   S[15] = r[4];
    mnmx<16>(S); S[0] = r[5]; S[15] = r[6];
    LOAD_SORT_ROW(6);
    mnmx<16>(S); S[0] = r[0]; S[15] = r[1];
    mnmx<16>(S); S[0] = r[2];            // live set: S[0..14], target rank 7

    // symmetric shrink to the median of 15
    mnmx<15>(S);
    mnmx<13>(S + 1);
    mnmx<11>(S + 2);
    mnmx<9>(S + 3);
    mnmx<7>(S + 4);
    mnmx<5>(S + 5);
    s2(S[6], S[7]); s2(S[7], S[8]); s2(S[6], S[7]);

    g_p[c * PLANE + oy * PATCH + ox] = S[7];
#undef LOAD_SORT_ROW
}

// ---------------------------------------------------------------------------
// Elementwise: out = clip(p*c + br + noise*0.1).
// 2 contiguous float4 per thread; pair never crosses a (b,f) slab boundary
// (boundaries are at float4 index 67500*s, always even).
// ---------------------------------------------------------------------------
#define TOTAL4 (BF_TOTAL * CHW / 4)     // 15,120,000
#define HALF4  (TOTAL4 / 2)             // 7,560,000

__global__ __launch_bounds__(256)
void apply_kernel(const float4* __restrict__ noise,
                  const float* __restrict__ contrast,
                  const float* __restrict__ brightness,
                  float4* __restrict__ out) {
    const unsigned gtid = blockIdx.x * 256u + threadIdx.x;
    if (gtid >= HALF4) return;

    const unsigned fi   = gtid * 2u;
    const unsigned flat = fi * 4u;                       // < 2^31
    const unsigned bf   = flat / (unsigned)CHW;
    const unsigned rem4 = (flat - bf * (unsigned)CHW) >> 2;

    // batch all loads up-front (MLP)
    const float4 n0 = __ldcs(noise + fi);
    const float4 n1 = __ldcs(noise + fi + 1);
    const float4* gp4 = reinterpret_cast<const float4*>(g_p);
    const float4 p0 = __ldg(gp4 + rem4);
    const float4 p1 = __ldg(gp4 + rem4 + 1);
    const float cc = __ldg(&contrast[bf]);
    const float bb = __ldg(&brightness[bf]);

    float4 r0, r1;
    r0.x = fminf(fmaxf(fmaf(n0.x, 0.1f, fmaf(p0.x, cc, bb)), 1e-6f), 0.99999f);
    r0.y = fminf(fmaxf(fmaf(n0.y, 0.1f, fmaf(p0.y, cc, bb)), 1e-6f), 0.99999f);
    r0.z = fminf(fmaxf(fmaf(n0.z, 0.1f, fmaf(p0.z, cc, bb)), 1e-6f), 0.99999f);
    r0.w = fminf(fmaxf(fmaf(n0.w, 0.1f, fmaf(p0.w, cc, bb)), 1e-6f), 0.99999f);
    r1.x = fminf(fmaxf(fmaf(n1.x, 0.1f, fmaf(p1.x, cc, bb)), 1e-6f), 0.99999f);
    r1.y = fminf(fmaxf(fmaf(n1.y, 0.1f, fmaf(p1.y, cc, bb)), 1e-6f), 0.99999f);
    r1.z = fminf(fmaxf(fmaf(n1.z, 0.1f, fmaf(p1.z, cc, bb)), 1e-6f), 0.99999f);
    r1.w = fminf(fmaxf(fmaf(n1.w, 0.1f, fmaf(p1.w, cc, bb)), 1e-6f), 0.99999f);

    __stcs(out + fi,     r0);
    __stcs(out + fi + 1, r1);
}

// ---------------------------------------------------------------------------
// Inputs (metadata order):
//   0: adv_patch  [3,300,300] f32
//   1: lab_batch  [16,14,5]   f32 (unused)
//   2: contrast   [16,14]     f32
//   3: brightness [16,14]     f32
//   4: noise      [16,14,3,300,300] f32
//   5: img_size   scalar (unused)
// Output: [16,14,3,300,300] f32
// ---------------------------------------------------------------------------
extern "C" void kernel_launch(void* const* d_in, const int* in_sizes, int n_in,
                              void* d_out, int out_size) {
    const float* adv_patch  = (const float*)d_in[0];
    const float* contrast   = (const float*)d_in[2];
    const float* brightness = (const float*)d_in[3];
    const float* noise      = (const float*)d_in[4];
    float* out = (float*)d_out;

    dim3 mblk(TBX, TBY, 1);
    dim3 mgrd((PATCH + TBX - 1) / TBX, (PATCH + TBY - 1) / TBY, CH);
    median7_kernel<<<mgrd, mblk>>>(adv_patch);

    const int blocks = (HALF4 + 255) / 256;
    apply_kernel<<<blocks, 256>>>((const float4*)noise, contrast, brightness,
                                  (float4*)out);
}